// round 13
// baseline (speedup 1.0000x reference)
#include <cuda_runtime.h>
#include <cstdint>
#include <math.h>

// Problem constants
#define B_    1024
#define F_    4096
#define V_    20000
#define E_    512
#define H_    1024
#define L_    20
#define D_    4
#define FOURH 4096

// ---------------------------------------------------------------------------
// Scratch (device globals — no allocation allowed)
// ---------------------------------------------------------------------------
__device__ float g_x[B_ * E_];
__device__ float g_h[B_ * H_];
__device__ float g_c[B_ * H_];
__device__ float g_gates[B_ * FOURH];
__device__ float g_logits[B_ * V_];
__device__ int   g_msg[L_ * B_];
__device__ float g_lp[B_];
__device__ float g_r[B_ * F_];
__device__ float g_ts[B_ * B_];
__device__ float g_ds[D_ * B_ * B_];
__device__ float g_rowLoss[B_];
__device__ float g_rowCorr[B_];

// ---------------------------------------------------------------------------
// mma.sync tf32 GEMM with 3xTF32 accuracy. R10: bigger warp tiles for reuse.
// C[M,N] = A0[M,K0]@W0[N,K0]^T (+ A1[M,K1]@W1[N,K1]^T) (+ bias0 + bias1)
// CTA tile 256x128, BK=16. 8 warps as 4x2; warp tile 64x64 (4mt x 8nt m16n8k8).
// Smem rows padded to 20 floats (fragment loads hit all 32 banks: 20g+t4).
// Double buffered cp.async. M % 256 == 0 required (all call sites satisfy).
// ---------------------------------------------------------------------------
#define BK     16
#define PADK   20
#define AROWS  256
#define BROWS  128
#define TILE_A_F (AROWS * PADK)          // 5120 floats
#define TILE_B_F (BROWS * PADK)          // 2560 floats
#define BUF_F    (TILE_A_F + TILE_B_F)   // 7680 floats
#define GEMM_SMEM (2 * BUF_F * 4)        // 61440 bytes

__device__ __forceinline__ uint32_t smem_u32(const void* p) {
    uint32_t a;
    asm("{ .reg .u64 t; cvta.to.shared.u64 t, %1; cvt.u32.u64 %0, t; }" : "=r"(a) : "l"(p));
    return a;
}

__device__ __forceinline__ void split1(float f, uint32_t& hi, uint32_t& lo) {
    uint32_t h;
    asm("cvt.rna.tf32.f32 %0, %1;" : "=r"(h) : "f"(f));
    float l = f - __uint_as_float(h);
    uint32_t lw;
    asm("cvt.rna.tf32.f32 %0, %1;" : "=r"(lw) : "f"(l));
    hi = h; lo = lw;
}

__device__ __forceinline__ void mma8(float* c, const uint32_t* a, const uint32_t* b) {
    asm volatile(
        "mma.sync.aligned.m16n8k8.row.col.f32.tf32.tf32.f32 "
        "{%0,%1,%2,%3}, {%4,%5,%6,%7}, {%8,%9}, {%0,%1,%2,%3};"
        : "+f"(c[0]), "+f"(c[1]), "+f"(c[2]), "+f"(c[3])
        : "r"(a[0]), "r"(a[1]), "r"(a[2]), "r"(a[3]), "r"(b[0]), "r"(b[1]));
}

__device__ __forceinline__ void cp16(uint32_t dst, const void* src, uint32_t srcsz) {
    asm volatile("cp.async.cg.shared.global [%0], [%1], 16, %2;"
                 :: "r"(dst), "l"(src), "r"(srcsz) : "memory");
}

// Load one 256x16 A tile + 128x16 W tile into buffer q via cp.async.
__device__ __forceinline__ void load_tile(
    uint32_t sb, int q, const float* __restrict__ A, const float* __restrict__ W,
    int K, int kb, int row0, int col0, int N, int t)
{
    const uint32_t abase = sb + (uint32_t)q * (BUF_F * 4u);
    const uint32_t bbase = abase + TILE_A_F * 4u;
#pragma unroll
    for (int i = 0; i < 4; i++) {          // A: 1024 cp16
        int ci = t + 256 * i;
        int row = ci >> 2;
        int c4 = (ci & 3) << 2;
        cp16(abase + (uint32_t)(row * PADK + c4) * 4u,
             A + (size_t)(row0 + row) * K + kb + c4, 16);
    }
#pragma unroll
    for (int i = 0; i < 2; i++) {          // B: 512 cp16
        int idx = t + 256 * i;
        int row = idx >> 2;
        int c4 = (idx & 3) << 2;
        int n = col0 + row;
        const float* wsrc = W + (size_t)(n < N ? n : 0) * K + kb + c4;
        cp16(bbase + (uint32_t)(row * PADK + c4) * 4u, wsrc, (n < N) ? 16u : 0u);
    }
}

__global__ __launch_bounds__(256) void gemm_mma(
    const float* __restrict__ A0, const float* __restrict__ W0, int K0,
    const float* __restrict__ A1, const float* __restrict__ W1, int K1,
    const float* __restrict__ bias0, const float* __restrict__ bias1,
    float* __restrict__ C, int M, int N)
{
    extern __shared__ float smemf[];
    const uint32_t sb = smem_u32(smemf);
    const int t = threadIdx.x, wid = t >> 5, lane = t & 31;
    const int g = lane >> 2, t4 = lane & 3;
    const int warp_m = wid & 3, warp_n = wid >> 2;   // 4 x 2
    const int row0 = blockIdx.y * 256, col0 = blockIdx.x * 128;

    const int T0 = K0 >> 4;
    const int T1 = A1 ? (K1 >> 4) : 0;
    const int T = T0 + T1;

    float acc[4][8][4];
#pragma unroll
    for (int mt = 0; mt < 4; mt++)
#pragma unroll
        for (int nt = 0; nt < 8; nt++)
#pragma unroll
            for (int i = 0; i < 4; i++) acc[mt][nt][i] = 0.f;

    // prologue: tile 0 -> buffer 0
    {
        const float* A = A0; const float* W = W0; int K = K0;
        if (T0 == 0) { A = A1; W = W1; K = K1; }
        load_tile(sb, 0, A, W, K, 0, row0, col0, N, t);
        asm volatile("cp.async.commit_group;" ::: "memory");
    }

    for (int tt = 0; tt < T; tt++) {
        if (tt + 1 < T) {
            int nt_ = tt + 1;
            const float* A; const float* W; int K, kb;
            if (nt_ < T0) { A = A0; W = W0; K = K0; kb = nt_ << 4; }
            else          { A = A1; W = W1; K = K1; kb = (nt_ - T0) << 4; }
            load_tile(sb, nt_ & 1, A, W, K, kb, row0, col0, N, t);
            asm volatile("cp.async.commit_group;" ::: "memory");
            asm volatile("cp.async.wait_group 1;" ::: "memory");
        } else {
            asm volatile("cp.async.wait_group 0;" ::: "memory");
        }
        __syncthreads();

        const float* As = smemf + (tt & 1) * BUF_F;
        const float* Bs = As + TILE_A_F;

#pragma unroll
        for (int kk = 0; kk < 2; kk++) {
            const int kb = kk * 8;
            uint32_t ahi[4][4], alo[4][4];
#pragma unroll
            for (int mt = 0; mt < 4; mt++) {
                const int mr = warp_m * 64 + mt * 16 + g;
                split1(As[mr * PADK + kb + t4],            ahi[mt][0], alo[mt][0]);
                split1(As[(mr + 8) * PADK + kb + t4],      ahi[mt][1], alo[mt][1]);
                split1(As[mr * PADK + kb + t4 + 4],        ahi[mt][2], alo[mt][2]);
                split1(As[(mr + 8) * PADK + kb + t4 + 4],  ahi[mt][3], alo[mt][3]);
            }
#pragma unroll
            for (int nt = 0; nt < 8; nt++) {
                const int nr = warp_n * 64 + nt * 8 + g;
                uint32_t bhi[2], blo[2];
                split1(Bs[nr * PADK + kb + t4],       bhi[0], blo[0]);
                split1(Bs[nr * PADK + kb + t4 + 4],   bhi[1], blo[1]);
#pragma unroll
                for (int mt = 0; mt < 4; mt++) {
                    mma8(acc[mt][nt], alo[mt], bhi);
                    mma8(acc[mt][nt], ahi[mt], blo);
                    mma8(acc[mt][nt], ahi[mt], bhi);
                }
            }
        }
        __syncthreads();
    }

    // epilogue
#pragma unroll
    for (int mt = 0; mt < 4; mt++) {
        const int rg = row0 + warp_m * 64 + mt * 16 + g;
#pragma unroll
        for (int nt = 0; nt < 8; nt++) {
            const int col = col0 + warp_n * 64 + nt * 8 + t4 * 2;
            if (col < N) {      // N even, col even -> col+1 valid too
                float bv0 = 0.f, bv1 = 0.f;
                if (bias0) { bv0 = bias0[col]; bv1 = bias0[col + 1]; }
                if (bias1) { bv0 += bias1[col]; bv1 += bias1[col + 1]; }
                float2 v0 = make_float2(acc[mt][nt][0] + bv0, acc[mt][nt][1] + bv1);
                float2 v1 = make_float2(acc[mt][nt][2] + bv0, acc[mt][nt][3] + bv1);
                *(float2*)(C + (size_t)rg * N + col) = v0;
                *(float2*)(C + (size_t)(rg + 8) * N + col) = v1;
            }
        }
    }
}

// ---------------------------------------------------------------------------
// LSTM pointwise update: gate order i, f, g, o
// ---------------------------------------------------------------------------
__device__ __forceinline__ float sigf(float x) { return 1.f / (1.f + expf(-x)); }

__global__ __launch_bounds__(256) void lstm_update(
    const float* __restrict__ gates, float* __restrict__ h, float* __restrict__ c)
{
    int idx = blockIdx.x * 256 + threadIdx.x;
    int b = idx >> 10;
    int j = idx & 1023;
    const float* g = gates + (size_t)b * FOURH;
    float ig = sigf(g[j]);
    float fg = sigf(g[H_ + j]);
    float gg = tanhf(g[2 * H_ + j]);
    float og = sigf(g[3 * H_ + j]);
    float cn = fg * c[idx] + ig * gg;
    c[idx] = cn;
    h[idx] = og * tanhf(cn);
}

// ---------------------------------------------------------------------------
// Per-row argmax + log-softmax value at argmax
// ---------------------------------------------------------------------------
__global__ __launch_bounds__(256) void row_argmax_lse(
    const float* __restrict__ logits, int* __restrict__ tok, float* __restrict__ lp)
{
    const int b = blockIdx.x, t = threadIdx.x;
    const float* row = logits + (size_t)b * V_;

    float m = -3.402823466e38f;
    int   mi = 0;
    for (int j = t; j < V_; j += 256) {
        float v = row[j];
        if (v > m) { m = v; mi = j; }
    }
    __shared__ float sm[256];
    __shared__ int   si[256];
    sm[t] = m; si[t] = mi;
    __syncthreads();
    for (int s = 128; s; s >>= 1) {
        if (t < s) {
            float vo = sm[t + s]; int io = si[t + s];
            if (vo > sm[t] || (vo == sm[t] && io < si[t])) { sm[t] = vo; si[t] = io; }
        }
        __syncthreads();
    }
    const float M = sm[0];
    const int   idx = si[0];

    float sum = 0.f;
    for (int j = t; j < V_; j += 256) sum += expf(row[j] - M);
    __shared__ float ss[256];
    ss[t] = sum;
    __syncthreads();
    for (int s = 128; s; s >>= 1) { if (t < s) ss[t] += ss[t + s]; __syncthreads(); }
    if (t == 0) { tok[b] = idx; lp[b] = -logf(ss[0]); }
}

// ---------------------------------------------------------------------------
// Embedding gather / start-token broadcast
// ---------------------------------------------------------------------------
__global__ __launch_bounds__(256) void gather_emb(
    const float* __restrict__ emb, const int* __restrict__ idx, float* __restrict__ x)
{
    int i = blockIdx.x * 256 + threadIdx.x;
    int b = i >> 9;
    int e = i & 511;
    x[i] = emb[(size_t)idx[b] * E_ + e];
}

__global__ __launch_bounds__(256) void init_x0(
    const float* __restrict__ emb_s, const int* __restrict__ start, float* __restrict__ x)
{
    int i = blockIdx.x * 256 + threadIdx.x;
    int e = i & 511;
    x[i] = emb_s[(size_t)(*start) * E_ + e];
}

// ---------------------------------------------------------------------------
// Hinge loss + accuracy
// ---------------------------------------------------------------------------
__global__ __launch_bounds__(256) void loss_acc_rows(
    const float* __restrict__ ts, const float* __restrict__ ds,
    const float* __restrict__ lp, float* __restrict__ rowLoss, float* __restrict__ rowCorr)
{
    const int i = blockIdx.x, t = threadIdx.x;
    const float* tsr = ts + (size_t)i * B_;
    const float* d0r = ds + (size_t)0 * B_ * B_ + (size_t)i * B_;
    const float* d1r = ds + (size_t)1 * B_ * B_ + (size_t)i * B_;
    const float* d2r = ds + (size_t)2 * B_ * B_ + (size_t)i * B_;
    const float* d3r = ds + (size_t)3 * B_ * B_ + (size_t)i * B_;

    float lsum = 0.f, tp = 0.f, dp0 = 0.f, dp1 = 0.f, dp2 = 0.f, dp3 = 0.f;
    for (int j = t; j < B_; j += 256) {
        float tv = tsr[j];
        float v0 = d0r[j], v1 = d1r[j], v2 = d2r[j], v3 = d3r[j];
        float hng = fmaxf(0.f, 1.f - tv + v0) + fmaxf(0.f, 1.f - tv + v1)
                  + fmaxf(0.f, 1.f - tv + v2) + fmaxf(0.f, 1.f - tv + v3);
        lsum += hng * (-lp[j]);
        tp  += expf(tv);
        dp0 += expf(v0); dp1 += expf(v1); dp2 += expf(v2); dp3 += expf(v3);
    }
    __shared__ float sh[6][256];
    sh[0][t] = lsum; sh[1][t] = tp; sh[2][t] = dp0;
    sh[3][t] = dp1;  sh[4][t] = dp2; sh[5][t] = dp3;
    __syncthreads();
    for (int s = 128; s; s >>= 1) {
        if (t < s)
#pragma unroll
            for (int q = 0; q < 6; q++) sh[q][t] += sh[q][t + s];
        __syncthreads();
    }
    if (t == 0) {
        rowLoss[i] = sh[0][0];
        float tpv = sh[1][0];
        rowCorr[i] = (tpv >= sh[2][0] && tpv >= sh[3][0] &&
                      tpv >= sh[4][0] && tpv >= sh[5][0]) ? 1.f : 0.f;
    }
}

__global__ __launch_bounds__(256) void finalize_k(
    const float* __restrict__ rowLoss, const float* __restrict__ rowCorr,
    float* __restrict__ out)
{
    const int t = threadIdx.x;
    float a = 0.f, b = 0.f;
    for (int i = t; i < B_; i += 256) { a += rowLoss[i]; b += rowCorr[i]; }
    __shared__ float sa[256], sb[256];
    sa[t] = a; sb[t] = b;
    __syncthreads();
    for (int s = 128; s; s >>= 1) {
        if (t < s) { sa[t] += sa[t + s]; sb[t] += sb[t + s]; }
        __syncthreads();
    }
    if (t == 0) {
        out[0] = sa[0] / ((float)B_ * (float)B_);
        out[1] = sb[0] / (float)B_;
    }
}

// ---------------------------------------------------------------------------
// Launch sequence
// ---------------------------------------------------------------------------
extern "C" void kernel_launch(void* const* d_in, const int* in_sizes, int n_in,
                              void* d_out, int out_size)
{
    (void)in_sizes; (void)n_in; (void)out_size;
    const float* target   = (const float*)d_in[0];
    const float* distr    = (const float*)d_in[1];
    const int*   start    = (const int*)  d_in[2];
    const float* emb_s    = (const float*)d_in[4];
    const float* Wih_s    = (const float*)d_in[5];
    const float* Whh_s    = (const float*)d_in[6];
    const float* bih_s    = (const float*)d_in[7];
    const float* bhh_s    = (const float*)d_in[8];
    const float* aff_s_W  = (const float*)d_in[9];
    const float* aff_s_b  = (const float*)d_in[10];
    const float* probs_W  = (const float*)d_in[11];
    const float* probs_b  = (const float*)d_in[12];
    const float* emb_r    = (const float*)d_in[13];
    const float* Wih_r    = (const float*)d_in[14];
    const float* Whh_r    = (const float*)d_in[15];
    const float* bih_r    = (const float*)d_in[16];
    const float* bhh_r    = (const float*)d_in[17];
    const float* aff_r_W  = (const float*)d_in[18];
    const float* aff_r_b  = (const float*)d_in[19];
    float* out = (float*)d_out;

    float *x, *h, *c, *gates, *logits, *lp, *r, *ts, *ds, *rowLoss, *rowCorr;
    int* msg;
    cudaGetSymbolAddress((void**)&x,       g_x);
    cudaGetSymbolAddress((void**)&h,       g_h);
    cudaGetSymbolAddress((void**)&c,       g_c);
    cudaGetSymbolAddress((void**)&gates,   g_gates);
    cudaGetSymbolAddress((void**)&logits,  g_logits);
    cudaGetSymbolAddress((void**)&msg,     g_msg);
    cudaGetSymbolAddress((void**)&lp,      g_lp);
    cudaGetSymbolAddress((void**)&r,       g_r);
    cudaGetSymbolAddress((void**)&ts,      g_ts);
    cudaGetSymbolAddress((void**)&ds,      g_ds);
    cudaGetSymbolAddress((void**)&rowLoss, g_rowLoss);
    cudaGetSymbolAddress((void**)&rowCorr, g_rowCorr);

    cudaFuncSetAttribute(gemm_mma, cudaFuncAttributeMaxDynamicSharedMemorySize, GEMM_SMEM);

    const float* NUL = (const float*)0;
    const dim3 gGate(FOURH / 128, B_ / 256);       // 32 x 4
    const dim3 gLogit((V_ + 127) / 128, B_ / 256); // 157 x 4

    // ---- Sender ----
    gemm_mma<<<dim3(H_ / 128, B_ / 256), 256, GEMM_SMEM>>>(
        target, aff_s_W, F_, NUL, NUL, 0, aff_s_b, NUL, h, B_, H_);
    cudaMemsetAsync(c, 0, sizeof(float) * B_ * H_);
    init_x0<<<(B_ * E_) / 256, 256>>>(emb_s, start, x);

    for (int t = 0; t < L_; t++) {
        gemm_mma<<<gGate, 256, GEMM_SMEM>>>(
            x, Wih_s, E_, h, Whh_s, H_, bih_s, bhh_s, gates, B_, FOURH);
        lstm_update<<<(B_ * H_) / 256, 256>>>(gates, h, c);
        gemm_mma<<<gLogit, 256, GEMM_SMEM>>>(
            h, probs_W, H_, NUL, NUL, 0, probs_b, NUL, logits, B_, V_);
        row_argmax_lse<<<B_, 256>>>(logits, msg + t * B_, lp);
        if (t + 1 < L_) gather_emb<<<(B_ * E_) / 256, 256>>>(emb_s, msg + t * B_, x);
    }

    // ---- Receiver ----
    cudaMemsetAsync(h, 0, sizeof(float) * B_ * H_);
    cudaMemsetAsync(c, 0, sizeof(float) * B_ * H_);
    for (int t = 0; t < L_; t++) {
        gather_emb<<<(B_ * E_) / 256, 256>>>(emb_r, msg + t * B_, x);
        gemm_mma<<<gGate, 256, GEMM_SMEM>>>(
            x, Wih_r, E_, h, Whh_r, H_, bih_r, bhh_r, gates, B_, FOURH);
        lstm_update<<<(B_ * H_) / 256, 256>>>(gates, h, c);
    }

    // ---- Scores + loss/accuracy ----
    gemm_mma<<<dim3(F_ / 128, B_ / 256), 256, GEMM_SMEM>>>(
        h, aff_r_W, H_, NUL, NUL, 0, aff_r_b, NUL, r, B_, F_);
    gemm_mma<<<dim3(B_ / 128, B_ / 256), 256, GEMM_SMEM>>>(
        target, r, F_, NUL, NUL, 0, NUL, NUL, ts, B_, B_);
    gemm_mma<<<dim3(B_ / 128, (D_ * B_) / 256), 256, GEMM_SMEM>>>(
        distr, r, F_, NUL, NUL, 0, NUL, NUL, ds, D_ * B_, B_);
    loss_acc_rows<<<B_, 256>>>(ts, ds, lp, rowLoss, rowCorr);
    finalize_k<<<1, 256>>>(rowLoss, rowCorr, out);
}

// round 15
// speedup vs baseline: 1.0378x; 1.0378x over previous
#include <cuda_runtime.h>
#include <cstdint>
#include <math.h>

// Problem constants
#define B_    1024
#define F_    4096
#define V_    20000
#define E_    512
#define H_    1024
#define L_    20
#define D_    4
#define FOURH 4096

// ---------------------------------------------------------------------------
// Scratch (device globals — no allocation allowed)
// ---------------------------------------------------------------------------
__device__ float g_x[B_ * E_];
__device__ float g_h[B_ * H_];
__device__ float g_c[B_ * H_];
__device__ float g_gates[B_ * FOURH];
__device__ float g_logits[B_ * V_];
__device__ int   g_msg[L_ * B_];
__device__ float g_lp[B_];
__device__ float g_r[B_ * F_];
__device__ float g_ts[B_ * B_];
__device__ float g_ds[D_ * B_ * B_];
__device__ float g_rowLoss[B_];
__device__ float g_rowCorr[B_];

// ---------------------------------------------------------------------------
// mma.sync tf32 GEMM, 3xTF32 accuracy. R14: Dekker split moved to the LOADER.
// Smem holds pre-split Ahi/Alo/Bhi/Blo tiles; inner loop is pure LDS + HMMA.
// C[M,N] = A0[M,K0]@W0[N,K0]^T (+ A1[M,K1]@W1[N,K1]^T) (+ bias0 + bias1)
// CTA tile 128x128, BK=32. 8 warps 2x4, warp tile 64x32 (R9 geometry).
// Manual LDG->regs->CVT->STS double-buffer pipeline (1 sync/tile).
// Smem: 2 x 4 x 128x36 floats = 147456 B. M%128==0, K%32==0 at all sites.
// ---------------------------------------------------------------------------
#define BK    32
#define PADK  36
#define ARR_F (128 * PADK)              // 4608 floats per array
#define BUF_F (4 * ARR_F)               // Ahi|Alo|Bhi|Blo
#define GEMM_SMEM (2 * BUF_F * 4)       // 147456 bytes

__device__ __forceinline__ void split1(float f, uint32_t& hi, uint32_t& lo) {
    uint32_t h;
    asm("cvt.rna.tf32.f32 %0, %1;" : "=r"(h) : "f"(f));
    float l = f - __uint_as_float(h);
    uint32_t lw;
    asm("cvt.rna.tf32.f32 %0, %1;" : "=r"(lw) : "f"(l));
    hi = h; lo = lw;
}

__device__ __forceinline__ void mma8(float* c, const uint32_t* a, const uint32_t* b) {
    asm volatile(
        "mma.sync.aligned.m16n8k8.row.col.f32.tf32.tf32.f32 "
        "{%0,%1,%2,%3}, {%4,%5,%6,%7}, {%8,%9}, {%0,%1,%2,%3};"
        : "+f"(c[0]), "+f"(c[1]), "+f"(c[2]), "+f"(c[3])
        : "r"(a[0]), "r"(a[1]), "r"(a[2]), "r"(a[3]), "r"(b[0]), "r"(b[1]));
}

// Load one 128x32 A slice + 128x32 W slice into registers (16+16 floats).
// Thread t: row = t>>1 (0..127), cols lcb..lcb+15 (lcb = (t&1)*16).
__device__ __forceinline__ void ldg_tile(
    float* areg, float* breg,
    const float* __restrict__ A, const float* __restrict__ W,
    int K, int kb, int row0, int col0, int N, int lrow, int lcb)
{
    const float* ap = A + (size_t)(row0 + lrow) * K + kb + lcb;
#pragma unroll
    for (int i = 0; i < 4; i++) *(float4*)(areg + 4 * i) = *(const float4*)(ap + 4 * i);
    const int n = col0 + lrow;
    if (n < N) {
        const float* wp = W + (size_t)n * K + kb + lcb;
#pragma unroll
        for (int i = 0; i < 4; i++) *(float4*)(breg + 4 * i) = *(const float4*)(wp + 4 * i);
    } else {
#pragma unroll
        for (int i = 0; i < 16; i++) breg[i] = 0.f;
    }
}

// Split staged registers and store hi/lo tiles into smem buffer q.
__device__ __forceinline__ void sts_tile(
    float* smemf, int q, const float* areg, const float* breg, int lrow, int lcb)
{
    float* base = smemf + q * BUF_F;
    float* Ahi = base;
    float* Alo = base + ARR_F;
    float* Bhi = base + 2 * ARR_F;
    float* Blo = base + 3 * ARR_F;
    const int off = lrow * PADK + lcb;
#pragma unroll
    for (int i = 0; i < 4; i++) {
        uint32_t h0, h1, h2, h3, l0, l1, l2, l3;
        split1(areg[4*i+0], h0, l0); split1(areg[4*i+1], h1, l1);
        split1(areg[4*i+2], h2, l2); split1(areg[4*i+3], h3, l3);
        *(float4*)&Ahi[off + 4*i] = make_float4(__uint_as_float(h0), __uint_as_float(h1),
                                                __uint_as_float(h2), __uint_as_float(h3));
        *(float4*)&Alo[off + 4*i] = make_float4(__uint_as_float(l0), __uint_as_float(l1),
                                                __uint_as_float(l2), __uint_as_float(l3));
        split1(breg[4*i+0], h0, l0); split1(breg[4*i+1], h1, l1);
        split1(breg[4*i+2], h2, l2); split1(breg[4*i+3], h3, l3);
        *(float4*)&Bhi[off + 4*i] = make_float4(__uint_as_float(h0), __uint_as_float(h1),
                                                __uint_as_float(h2), __uint_as_float(h3));
        *(float4*)&Blo[off + 4*i] = make_float4(__uint_as_float(l0), __uint_as_float(l1),
                                                __uint_as_float(l2), __uint_as_float(l3));
    }
}

__global__ __launch_bounds__(256) void gemm_mma(
    const float* __restrict__ A0, const float* __restrict__ W0, int K0,
    const float* __restrict__ A1, const float* __restrict__ W1, int K1,
    const float* __restrict__ bias0, const float* __restrict__ bias1,
    float* __restrict__ C, int M, int N)
{
    extern __shared__ float smemf[];
    const int t = threadIdx.x, wid = t >> 5, lane = t & 31;
    const int g = lane >> 2, t4 = lane & 3;
    const int warp_m = wid & 1, warp_n = wid >> 1;   // 2 x 4
    const int row0 = blockIdx.y * 128, col0 = blockIdx.x * 128;
    const int lrow = t >> 1, lcb = (t & 1) * 16;

    const int T0 = K0 >> 5;
    const int T1 = A1 ? (K1 >> 5) : 0;
    const int T = T0 + T1;

    float acc[4][4][4];
#pragma unroll
    for (int mt = 0; mt < 4; mt++)
#pragma unroll
        for (int nt = 0; nt < 4; nt++)
#pragma unroll
            for (int i = 0; i < 4; i++) acc[mt][nt][i] = 0.f;

    float areg[16], breg[16];

    // prologue: tile 0 -> regs -> smem buffer 0
    {
        const float* A = A0; const float* W = W0; int K = K0;
        if (T0 == 0) { A = A1; W = W1; K = K1; }
        ldg_tile(areg, breg, A, W, K, 0, row0, col0, N, lrow, lcb);
    }
    sts_tile(smemf, 0, areg, breg, lrow, lcb);

    for (int tt = 0; tt < T; tt++) {
        __syncthreads();                       // buffer tt&1 visible to all
        if (tt + 1 < T) {                      // LDG for next tile (latency hidden by compute)
            int nx = tt + 1;
            const float* A; const float* W; int K, kb;
            if (nx < T0) { A = A0; W = W0; K = K0; kb = nx << 5; }
            else         { A = A1; W = W1; K = K1; kb = (nx - T0) << 5; }
            ldg_tile(areg, breg, A, W, K, kb, row0, col0, N, lrow, lcb);
        }

        const float* base = smemf + (tt & 1) * BUF_F;
        const float* Ahi = base;
        const float* Alo = base + ARR_F;
        const float* Bhi = base + 2 * ARR_F;
        const float* Blo = base + 3 * ARR_F;

#pragma unroll
        for (int kk = 0; kk < 4; kk++) {
            const int kb = kk * 8;
            uint32_t ahi[4][4], alo[4][4];
#pragma unroll
            for (int mt = 0; mt < 4; mt++) {
                const int mr = warp_m * 64 + mt * 16 + g;
                ahi[mt][0] = __float_as_uint(Ahi[mr * PADK + kb + t4]);
                alo[mt][0] = __float_as_uint(Alo[mr * PADK + kb + t4]);
                ahi[mt][1] = __float_as_uint(Ahi[(mr + 8) * PADK + kb + t4]);
                alo[mt][1] = __float_as_uint(Alo[(mr + 8) * PADK + kb + t4]);
                ahi[mt][2] = __float_as_uint(Ahi[mr * PADK + kb + t4 + 4]);
                alo[mt][2] = __float_as_uint(Alo[mr * PADK + kb + t4 + 4]);
                ahi[mt][3] = __float_as_uint(Ahi[(mr + 8) * PADK + kb + t4 + 4]);
                alo[mt][3] = __float_as_uint(Alo[(mr + 8) * PADK + kb + t4 + 4]);
            }
            uint32_t bhi[4][2], blo[4][2];
#pragma unroll
            for (int nt = 0; nt < 4; nt++) {
                const int nr = warp_n * 32 + nt * 8 + g;
                bhi[nt][0] = __float_as_uint(Bhi[nr * PADK + kb + t4]);
                blo[nt][0] = __float_as_uint(Blo[nr * PADK + kb + t4]);
                bhi[nt][1] = __float_as_uint(Bhi[nr * PADK + kb + t4 + 4]);
                blo[nt][1] = __float_as_uint(Blo[nr * PADK + kb + t4 + 4]);
            }
#pragma unroll
            for (int mt = 0; mt < 4; mt++)
#pragma unroll
                for (int nt = 0; nt < 4; nt++) {
                    mma8(acc[mt][nt], alo[mt], bhi[nt]);
                    mma8(acc[mt][nt], ahi[mt], blo[nt]);
                    mma8(acc[mt][nt], ahi[mt], bhi[nt]);
                }
        }
        if (tt + 1 < T)                        // split+store next tile into other buffer
            sts_tile(smemf, (tt + 1) & 1, areg, breg, lrow, lcb);
    }

    // epilogue
#pragma unroll
    for (int mt = 0; mt < 4; mt++) {
        const int rg = row0 + warp_m * 64 + mt * 16 + g;
#pragma unroll
        for (int nt = 0; nt < 4; nt++) {
            const int col = col0 + warp_n * 32 + nt * 8 + t4 * 2;
            if (col < N) {      // N even, col even -> col+1 valid too
                float bv0 = 0.f, bv1 = 0.f;
                if (bias0) { bv0 = bias0[col]; bv1 = bias0[col + 1]; }
                if (bias1) { bv0 += bias1[col]; bv1 += bias1[col + 1]; }
                float2 v0 = make_float2(acc[mt][nt][0] + bv0, acc[mt][nt][1] + bv1);
                float2 v1 = make_float2(acc[mt][nt][2] + bv0, acc[mt][nt][3] + bv1);
                *(float2*)(C + (size_t)rg * N + col) = v0;
                *(float2*)(C + (size_t)(rg + 8) * N + col) = v1;
            }
        }
    }
}

// ---------------------------------------------------------------------------
// LSTM pointwise update: gate order i, f, g, o
// ---------------------------------------------------------------------------
__device__ __forceinline__ float sigf(float x) { return 1.f / (1.f + expf(-x)); }

__global__ __launch_bounds__(256) void lstm_update(
    const float* __restrict__ gates, float* __restrict__ h, float* __restrict__ c)
{
    int idx = blockIdx.x * 256 + threadIdx.x;
    int b = idx >> 10;
    int j = idx & 1023;
    const float* g = gates + (size_t)b * FOURH;
    float ig = sigf(g[j]);
    float fg = sigf(g[H_ + j]);
    float gg = tanhf(g[2 * H_ + j]);
    float og = sigf(g[3 * H_ + j]);
    float cn = fg * c[idx] + ig * gg;
    c[idx] = cn;
    h[idx] = og * tanhf(cn);
}

// ---------------------------------------------------------------------------
// Per-row argmax + log-softmax value at argmax
// ---------------------------------------------------------------------------
__global__ __launch_bounds__(256) void row_argmax_lse(
    const float* __restrict__ logits, int* __restrict__ tok, float* __restrict__ lp)
{
    const int b = blockIdx.x, t = threadIdx.x;
    const float* row = logits + (size_t)b * V_;

    float m = -3.402823466e38f;
    int   mi = 0;
    for (int j = t; j < V_; j += 256) {
        float v = row[j];
        if (v > m) { m = v; mi = j; }
    }
    __shared__ float sm[256];
    __shared__ int   si[256];
    sm[t] = m; si[t] = mi;
    __syncthreads();
    for (int s = 128; s; s >>= 1) {
        if (t < s) {
            float vo = sm[t + s]; int io = si[t + s];
            if (vo > sm[t] || (vo == sm[t] && io < si[t])) { sm[t] = vo; si[t] = io; }
        }
        __syncthreads();
    }
    const float M = sm[0];
    const int   idx = si[0];

    float sum = 0.f;
    for (int j = t; j < V_; j += 256) sum += expf(row[j] - M);
    __shared__ float ss[256];
    ss[t] = sum;
    __syncthreads();
    for (int s = 128; s; s >>= 1) { if (t < s) ss[t] += ss[t + s]; __syncthreads(); }
    if (t == 0) { tok[b] = idx; lp[b] = -logf(ss[0]); }
}

// ---------------------------------------------------------------------------
// Embedding gather / start-token broadcast
// ---------------------------------------------------------------------------
__global__ __launch_bounds__(256) void gather_emb(
    const float* __restrict__ emb, const int* __restrict__ idx, float* __restrict__ x)
{
    int i = blockIdx.x * 256 + threadIdx.x;
    int b = i >> 9;
    int e = i & 511;
    x[i] = emb[(size_t)idx[b] * E_ + e];
}

__global__ __launch_bounds__(256) void init_x0(
    const float* __restrict__ emb_s, const int* __restrict__ start, float* __restrict__ x)
{
    int i = blockIdx.x * 256 + threadIdx.x;
    int e = i & 511;
    x[i] = emb_s[(size_t)(*start) * E_ + e];
}

// ---------------------------------------------------------------------------
// Hinge loss + accuracy
// ---------------------------------------------------------------------------
__global__ __launch_bounds__(256) void loss_acc_rows(
    const float* __restrict__ ts, const float* __restrict__ ds,
    const float* __restrict__ lp, float* __restrict__ rowLoss, float* __restrict__ rowCorr)
{
    const int i = blockIdx.x, t = threadIdx.x;
    const float* tsr = ts + (size_t)i * B_;
    const float* d0r = ds + (size_t)0 * B_ * B_ + (size_t)i * B_;
    const float* d1r = ds + (size_t)1 * B_ * B_ + (size_t)i * B_;
    const float* d2r = ds + (size_t)2 * B_ * B_ + (size_t)i * B_;
    const float* d3r = ds + (size_t)3 * B_ * B_ + (size_t)i * B_;

    float lsum = 0.f, tp = 0.f, dp0 = 0.f, dp1 = 0.f, dp2 = 0.f, dp3 = 0.f;
    for (int j = t; j < B_; j += 256) {
        float tv = tsr[j];
        float v0 = d0r[j], v1 = d1r[j], v2 = d2r[j], v3 = d3r[j];
        float hng = fmaxf(0.f, 1.f - tv + v0) + fmaxf(0.f, 1.f - tv + v1)
                  + fmaxf(0.f, 1.f - tv + v2) + fmaxf(0.f, 1.f - tv + v3);
        lsum += hng * (-lp[j]);
        tp  += expf(tv);
        dp0 += expf(v0); dp1 += expf(v1); dp2 += expf(v2); dp3 += expf(v3);
    }
    __shared__ float sh[6][256];
    sh[0][t] = lsum; sh[1][t] = tp; sh[2][t] = dp0;
    sh[3][t] = dp1;  sh[4][t] = dp2; sh[5][t] = dp3;
    __syncthreads();
    for (int s = 128; s; s >>= 1) {
        if (t < s)
#pragma unroll
            for (int q = 0; q < 6; q++) sh[q][t] += sh[q][t + s];
        __syncthreads();
    }
    if (t == 0) {
        rowLoss[i] = sh[0][0];
        float tpv = sh[1][0];
        rowCorr[i] = (tpv >= sh[2][0] && tpv >= sh[3][0] &&
                      tpv >= sh[4][0] && tpv >= sh[5][0]) ? 1.f : 0.f;
    }
}

__global__ __launch_bounds__(256) void finalize_k(
    const float* __restrict__ rowLoss, const float* __restrict__ rowCorr,
    float* __restrict__ out)
{
    const int t = threadIdx.x;
    float a = 0.f, b = 0.f;
    for (int i = t; i < B_; i += 256) { a += rowLoss[i]; b += rowCorr[i]; }
    __shared__ float sa[256], sb[256];
    sa[t] = a; sb[t] = b;
    __syncthreads();
    for (int s = 128; s; s >>= 1) {
        if (t < s) { sa[t] += sa[t + s]; sb[t] += sb[t + s]; }
        __syncthreads();
    }
    if (t == 0) {
        out[0] = sa[0] / ((float)B_ * (float)B_);
        out[1] = sb[0] / (float)B_;
    }
}

// ---------------------------------------------------------------------------
// Launch sequence
// ---------------------------------------------------------------------------
extern "C" void kernel_launch(void* const* d_in, const int* in_sizes, int n_in,
                              void* d_out, int out_size)
{
    (void)in_sizes; (void)n_in; (void)out_size;
    const float* target   = (const float*)d_in[0];
    const float* distr    = (const float*)d_in[1];
    const int*   start    = (const int*)  d_in[2];
    const float* emb_s    = (const float*)d_in[4];
    const float* Wih_s    = (const float*)d_in[5];
    const float* Whh_s    = (const float*)d_in[6];
    const float* bih_s    = (const float*)d_in[7];
    const float* bhh_s    = (const float*)d_in[8];
    const float* aff_s_W  = (const float*)d_in[9];
    const float* aff_s_b  = (const float*)d_in[10];
    const float* probs_W  = (const float*)d_in[11];
    const float* probs_b  = (const float*)d_in[12];
    const float* emb_r    = (const float*)d_in[13];
    const float* Wih_r    = (const float*)d_in[14];
    const float* Whh_r    = (const float*)d_in[15];
    const float* bih_r    = (const float*)d_in[16];
    const float* bhh_r    = (const float*)d_in[17];
    const float* aff_r_W  = (const float*)d_in[18];
    const float* aff_r_b  = (const float*)d_in[19];
    float* out = (float*)d_out;

    float *x, *h, *c, *gates, *logits, *lp, *r, *ts, *ds, *rowLoss, *rowCorr;
    int* msg;
    cudaGetSymbolAddress((void**)&x,       g_x);
    cudaGetSymbolAddress((void**)&h,       g_h);
    cudaGetSymbolAddress((void**)&c,       g_c);
    cudaGetSymbolAddress((void**)&gates,   g_gates);
    cudaGetSymbolAddress((void**)&logits,  g_logits);
    cudaGetSymbolAddress((void**)&msg,     g_msg);
    cudaGetSymbolAddress((void**)&lp,      g_lp);
    cudaGetSymbolAddress((void**)&r,       g_r);
    cudaGetSymbolAddress((void**)&ts,      g_ts);
    cudaGetSymbolAddress((void**)&ds,      g_ds);
    cudaGetSymbolAddress((void**)&rowLoss, g_rowLoss);
    cudaGetSymbolAddress((void**)&rowCorr, g_rowCorr);

    cudaFuncSetAttribute(gemm_mma, cudaFuncAttributeMaxDynamicSharedMemorySize, GEMM_SMEM);

    const float* NUL = (const float*)0;
    const dim3 gGate(FOURH / 128, B_ / 128);       // 32 x 8
    const dim3 gLogit((V_ + 127) / 128, B_ / 128); // 157 x 8

    // ---- Sender ----
    gemm_mma<<<dim3(H_ / 128, B_ / 128), 256, GEMM_SMEM>>>(
        target, aff_s_W, F_, NUL, NUL, 0, aff_s_b, NUL, h, B_, H_);
    cudaMemsetAsync(c, 0, sizeof(float) * B_ * H_);
    init_x0<<<(B_ * E_) / 256, 256>>>(emb_s, start, x);

    for (int t = 0; t < L_; t++) {
        gemm_mma<<<gGate, 256, GEMM_SMEM>>>(
            x, Wih_s, E_, h, Whh_s, H_, bih_s, bhh_s, gates, B_, FOURH);
        lstm_update<<<(B_ * H_) / 256, 256>>>(gates, h, c);
        gemm_mma<<<gLogit, 256, GEMM_SMEM>>>(
            h, probs_W, H_, NUL, NUL, 0, probs_b, NUL, logits, B_, V_);
        row_argmax_lse<<<B_, 256>>>(logits, msg + t * B_, lp);
        if (t + 1 < L_) gather_emb<<<(B_ * E_) / 256, 256>>>(emb_s, msg + t * B_, x);
    }

    // ---- Receiver ----
    cudaMemsetAsync(h, 0, sizeof(float) * B_ * H_);
    cudaMemsetAsync(c, 0, sizeof(float) * B_ * H_);
    for (int t = 0; t < L_; t++) {
        gather_emb<<<(B_ * E_) / 256, 256>>>(emb_r, msg + t * B_, x);
        gemm_mma<<<gGate, 256, GEMM_SMEM>>>(
            x, Wih_r, E_, h, Whh_r, H_, bih_r, bhh_r, gates, B_, FOURH);
        lstm_update<<<(B_ * H_) / 256, 256>>>(gates, h, c);
    }

    // ---- Scores + loss/accuracy ----
    gemm_mma<<<dim3(F_ / 128, B_ / 128), 256, GEMM_SMEM>>>(
        h, aff_r_W, H_, NUL, NUL, 0, aff_r_b, NUL, r, B_, F_);
    gemm_mma<<<dim3(B_ / 128, B_ / 128), 256, GEMM_SMEM>>>(
        target, r, F_, NUL, NUL, 0, NUL, NUL, ts, B_, B_);
    gemm_mma<<<dim3(B_ / 128, (D_ * B_) / 128), 256, GEMM_SMEM>>>(
        distr, r, F_, NUL, NUL, 0, NUL, NUL, ds, D_ * B_, B_);
    loss_acc_rows<<<B_, 256>>>(ts, ds, lp, rowLoss, rowCorr);
    finalize_k<<<1, 256>>>(rowLoss, rowCorr, out);
}

// round 17
// speedup vs baseline: 1.3551x; 1.3058x over previous
#include <cuda_runtime.h>
#include <cstdint>
#include <math.h>

// Problem constants
#define B_    1024
#define F_    4096
#define V_    20000
#define E_    512
#define H_    1024
#define L_    20
#define D_    4
#define FOURH 4096

// ---------------------------------------------------------------------------
// Scratch (device globals — no allocation allowed)
// ---------------------------------------------------------------------------
__device__ float g_x[B_ * E_];
__device__ float g_h[B_ * H_];
__device__ float g_c[B_ * H_];
__device__ float g_gates[B_ * FOURH];
__device__ float g_logits[B_ * V_];
__device__ int   g_msg[L_ * B_];
__device__ float g_lp[B_];
__device__ float g_r[B_ * F_];
__device__ float g_ts[B_ * B_];
__device__ float g_ds[D_ * B_ * B_];
__device__ float g_rowLoss[B_];
__device__ float g_rowCorr[B_];

// ---------------------------------------------------------------------------
// mma.sync tf32 GEMM with 3xTF32 accuracy. R16 = R9 structure, but the Dekker
// split uses BIT-MASK truncation (AND + FSUB + AND, cheap pipes) instead of
// cvt.rna.tf32 (quarter-rate F2FP pipe) — removes the measured CVT bottleneck.
// C[M,N] = A0[M,K0]@W0[N,K0]^T (+ A1[M,K1]@W1[N,K1]^T) (+ bias0 + bias1)
// 128x128x32 tiles, 256 threads (8 warps, 2x4), warp tile 64x32 (4x4 m16n8k8).
// Smem: raw fp32 tiles, row-major [128][36] padded, double buffered cp.async.
// ---------------------------------------------------------------------------
#define PADK 36
#define TILE_F (128 * PADK)            // floats per tile buffer (4608)
#define GEMM_SMEM (2 * 2 * TILE_F * 4) // 73728 bytes

__device__ __forceinline__ uint32_t smem_u32(const void* p) {
    uint32_t a;
    asm("{ .reg .u64 t; cvta.to.shared.u64 t, %1; cvt.u32.u64 %0, t; }" : "=r"(a) : "l"(p));
    return a;
}

// tf32 Dekker split via mantissa truncation: hi keeps the top 10 explicit
// mantissa bits (canonical tf32 bit pattern), lo = f - hi (exact in fp32),
// then lo is also truncated to a canonical tf32 pattern. No CVT instructions.
__device__ __forceinline__ void split1(float f, uint32_t& hi, uint32_t& lo) {
    uint32_t u = __float_as_uint(f);
    hi = u & 0xFFFFE000u;
    float l = f - __uint_as_float(hi);
    lo = __float_as_uint(l) & 0xFFFFE000u;
}

__device__ __forceinline__ void mma8(float* c, const uint32_t* a, const uint32_t* b) {
    asm volatile(
        "mma.sync.aligned.m16n8k8.row.col.f32.tf32.tf32.f32 "
        "{%0,%1,%2,%3}, {%4,%5,%6,%7}, {%8,%9}, {%0,%1,%2,%3};"
        : "+f"(c[0]), "+f"(c[1]), "+f"(c[2]), "+f"(c[3])
        : "r"(a[0]), "r"(a[1]), "r"(a[2]), "r"(a[3]), "r"(b[0]), "r"(b[1]));
}

__device__ __forceinline__ void cp16(uint32_t dst, const void* src, uint32_t srcsz) {
    asm volatile("cp.async.cg.shared.global [%0], [%1], 16, %2;"
                 :: "r"(dst), "l"(src), "r"(srcsz) : "memory");
}

// Load one 128x32 A tile + 128x32 W tile into buffer q via cp.async.
__device__ __forceinline__ void load_tile(
    uint32_t sb, int q, const float* __restrict__ A, const float* __restrict__ W,
    int K, int kb, int row0, int col0, int N, int t)
{
    const uint32_t abase = sb + (uint32_t)q * (2u * TILE_F * 4u);
    const uint32_t bbase = abase + TILE_F * 4u;
#pragma unroll
    for (int i = 0; i < 4; i++) {
        int ci = t + 256 * i;           // 0..1023
        int row = ci >> 3;
        int cc = ci & 7;
        uint32_t off = (uint32_t)(row * PADK + cc * 4) * 4u;
        cp16(abase + off, A + (size_t)(row0 + row) * K + kb + cc * 4, 16);
        int n = col0 + row;
        const float* wsrc = W + (size_t)(n < N ? n : 0) * K + kb + cc * 4;
        cp16(bbase + off, wsrc, (n < N) ? 16u : 0u);
    }
}

__global__ __launch_bounds__(256) void gemm_mma(
    const float* __restrict__ A0, const float* __restrict__ W0, int K0,
    const float* __restrict__ A1, const float* __restrict__ W1, int K1,
    const float* __restrict__ bias0, const float* __restrict__ bias1,
    float* __restrict__ C, int M, int N)
{
    extern __shared__ float smemf[];
    const uint32_t sb = smem_u32(smemf);
    const int t = threadIdx.x, wid = t >> 5, lane = t & 31;
    const int g = lane >> 2, t4 = lane & 3;
    const int warp_m = wid & 1, warp_n = wid >> 1;   // 2 x 4
    const int row0 = blockIdx.y * 128, col0 = blockIdx.x * 128;

    const int T0 = K0 >> 5;
    const int T1 = A1 ? (K1 >> 5) : 0;
    const int T = T0 + T1;

    float acc[4][4][4];
#pragma unroll
    for (int mt = 0; mt < 4; mt++)
#pragma unroll
        for (int nt = 0; nt < 4; nt++)
#pragma unroll
            for (int i = 0; i < 4; i++) acc[mt][nt][i] = 0.f;

    // prologue: tile 0 -> buffer 0
    {
        const float* A = A0; const float* W = W0; int K = K0;
        if (T0 == 0) { A = A1; W = W1; K = K1; }
        load_tile(sb, 0, A, W, K, 0, row0, col0, N, t);
        asm volatile("cp.async.commit_group;" ::: "memory");
    }

    for (int tt = 0; tt < T; tt++) {
        if (tt + 1 < T) {
            int nt_ = tt + 1;
            const float* A; const float* W; int K, kb;
            if (nt_ < T0) { A = A0; W = W0; K = K0; kb = nt_ << 5; }
            else          { A = A1; W = W1; K = K1; kb = (nt_ - T0) << 5; }
            load_tile(sb, nt_ & 1, A, W, K, kb, row0, col0, N, t);
            asm volatile("cp.async.commit_group;" ::: "memory");
            asm volatile("cp.async.wait_group 1;" ::: "memory");
        } else {
            asm volatile("cp.async.wait_group 0;" ::: "memory");
        }
        __syncthreads();

        const float* As = smemf + (tt & 1) * (2 * TILE_F);
        const float* Bs = As + TILE_F;

#pragma unroll
        for (int kk = 0; kk < 4; kk++) {
            const int kb = kk * 8;
            uint32_t ahi[4][4], alo[4][4];
#pragma unroll
            for (int mt = 0; mt < 4; mt++) {
                const int mr = warp_m * 64 + mt * 16 + g;
                split1(As[mr * PADK + kb + t4],            ahi[mt][0], alo[mt][0]);
                split1(As[(mr + 8) * PADK + kb + t4],      ahi[mt][1], alo[mt][1]);
                split1(As[mr * PADK + kb + t4 + 4],        ahi[mt][2], alo[mt][2]);
                split1(As[(mr + 8) * PADK + kb + t4 + 4],  ahi[mt][3], alo[mt][3]);
            }
            uint32_t bhi[4][2], blo[4][2];
#pragma unroll
            for (int nt = 0; nt < 4; nt++) {
                const int nr = warp_n * 32 + nt * 8 + g;
                split1(Bs[nr * PADK + kb + t4],       bhi[nt][0], blo[nt][0]);
                split1(Bs[nr * PADK + kb + t4 + 4],   bhi[nt][1], blo[nt][1]);
            }
#pragma unroll
            for (int mt = 0; mt < 4; mt++)
#pragma unroll
                for (int nt = 0; nt < 4; nt++) {
                    mma8(acc[mt][nt], alo[mt], bhi[nt]);
                    mma8(acc[mt][nt], ahi[mt], blo[nt]);
                    mma8(acc[mt][nt], ahi[mt], bhi[nt]);
                }
        }
        __syncthreads();
    }

    // epilogue
#pragma unroll
    for (int mt = 0; mt < 4; mt++) {
        const int rg = row0 + warp_m * 64 + mt * 16 + g;
#pragma unroll
        for (int nt = 0; nt < 4; nt++) {
            const int col = col0 + warp_n * 32 + nt * 8 + t4 * 2;
            if (col < N) {      // N even, col even -> col+1 valid too
                float bv0 = 0.f, bv1 = 0.f;
                if (bias0) { bv0 = bias0[col]; bv1 = bias0[col + 1]; }
                if (bias1) { bv0 += bias1[col]; bv1 += bias1[col + 1]; }
                float2 v0 = make_float2(acc[mt][nt][0] + bv0, acc[mt][nt][1] + bv1);
                float2 v1 = make_float2(acc[mt][nt][2] + bv0, acc[mt][nt][3] + bv1);
                *(float2*)(C + (size_t)rg * N + col) = v0;
                *(float2*)(C + (size_t)(rg + 8) * N + col) = v1;
            }
        }
    }
}

// ---------------------------------------------------------------------------
// LSTM pointwise update: gate order i, f, g, o
// ---------------------------------------------------------------------------
__device__ __forceinline__ float sigf(float x) { return 1.f / (1.f + expf(-x)); }

__global__ __launch_bounds__(256) void lstm_update(
    const float* __restrict__ gates, float* __restrict__ h, float* __restrict__ c)
{
    int idx = blockIdx.x * 256 + threadIdx.x;
    int b = idx >> 10;
    int j = idx & 1023;
    const float* g = gates + (size_t)b * FOURH;
    float ig = sigf(g[j]);
    float fg = sigf(g[H_ + j]);
    float gg = tanhf(g[2 * H_ + j]);
    float og = sigf(g[3 * H_ + j]);
    float cn = fg * c[idx] + ig * gg;
    c[idx] = cn;
    h[idx] = og * tanhf(cn);
}

// ---------------------------------------------------------------------------
// Per-row argmax + log-softmax value at argmax
// ---------------------------------------------------------------------------
__global__ __launch_bounds__(256) void row_argmax_lse(
    const float* __restrict__ logits, int* __restrict__ tok, float* __restrict__ lp)
{
    const int b = blockIdx.x, t = threadIdx.x;
    const float* row = logits + (size_t)b * V_;

    float m = -3.402823466e38f;
    int   mi = 0;
    for (int j = t; j < V_; j += 256) {
        float v = row[j];
        if (v > m) { m = v; mi = j; }
    }
    __shared__ float sm[256];
    __shared__ int   si[256];
    sm[t] = m; si[t] = mi;
    __syncthreads();
    for (int s = 128; s; s >>= 1) {
        if (t < s) {
            float vo = sm[t + s]; int io = si[t + s];
            if (vo > sm[t] || (vo == sm[t] && io < si[t])) { sm[t] = vo; si[t] = io; }
        }
        __syncthreads();
    }
    const float M = sm[0];
    const int   idx = si[0];

    float sum = 0.f;
    for (int j = t; j < V_; j += 256) sum += expf(row[j] - M);
    __shared__ float ss[256];
    ss[t] = sum;
    __syncthreads();
    for (int s = 128; s; s >>= 1) { if (t < s) ss[t] += ss[t + s]; __syncthreads(); }
    if (t == 0) { tok[b] = idx; lp[b] = -logf(ss[0]); }
}

// ---------------------------------------------------------------------------
// Embedding gather / start-token broadcast
// ---------------------------------------------------------------------------
__global__ __launch_bounds__(256) void gather_emb(
    const float* __restrict__ emb, const int* __restrict__ idx, float* __restrict__ x)
{
    int i = blockIdx.x * 256 + threadIdx.x;
    int b = i >> 9;
    int e = i & 511;
    x[i] = emb[(size_t)idx[b] * E_ + e];
}

__global__ __launch_bounds__(256) void init_x0(
    const float* __restrict__ emb_s, const int* __restrict__ start, float* __restrict__ x)
{
    int i = blockIdx.x * 256 + threadIdx.x;
    int e = i & 511;
    x[i] = emb_s[(size_t)(*start) * E_ + e];
}

// ---------------------------------------------------------------------------
// Hinge loss + accuracy
// ---------------------------------------------------------------------------
__global__ __launch_bounds__(256) void loss_acc_rows(
    const float* __restrict__ ts, const float* __restrict__ ds,
    const float* __restrict__ lp, float* __restrict__ rowLoss, float* __restrict__ rowCorr)
{
    const int i = blockIdx.x, t = threadIdx.x;
    const float* tsr = ts + (size_t)i * B_;
    const float* d0r = ds + (size_t)0 * B_ * B_ + (size_t)i * B_;
    const float* d1r = ds + (size_t)1 * B_ * B_ + (size_t)i * B_;
    const float* d2r = ds + (size_t)2 * B_ * B_ + (size_t)i * B_;
    const float* d3r = ds + (size_t)3 * B_ * B_ + (size_t)i * B_;

    float lsum = 0.f, tp = 0.f, dp0 = 0.f, dp1 = 0.f, dp2 = 0.f, dp3 = 0.f;
    for (int j = t; j < B_; j += 256) {
        float tv = tsr[j];
        float v0 = d0r[j], v1 = d1r[j], v2 = d2r[j], v3 = d3r[j];
        float hng = fmaxf(0.f, 1.f - tv + v0) + fmaxf(0.f, 1.f - tv + v1)
                  + fmaxf(0.f, 1.f - tv + v2) + fmaxf(0.f, 1.f - tv + v3);
        lsum += hng * (-lp[j]);
        tp  += expf(tv);
        dp0 += expf(v0); dp1 += expf(v1); dp2 += expf(v2); dp3 += expf(v3);
    }
    __shared__ float sh[6][256];
    sh[0][t] = lsum; sh[1][t] = tp; sh[2][t] = dp0;
    sh[3][t] = dp1;  sh[4][t] = dp2; sh[5][t] = dp3;
    __syncthreads();
    for (int s = 128; s; s >>= 1) {
        if (t < s)
#pragma unroll
            for (int q = 0; q < 6; q++) sh[q][t] += sh[q][t + s];
        __syncthreads();
    }
    if (t == 0) {
        rowLoss[i] = sh[0][0];
        float tpv = sh[1][0];
        rowCorr[i] = (tpv >= sh[2][0] && tpv >= sh[3][0] &&
                      tpv >= sh[4][0] && tpv >= sh[5][0]) ? 1.f : 0.f;
    }
}

__global__ __launch_bounds__(256) void finalize_k(
    const float* __restrict__ rowLoss, const float* __restrict__ rowCorr,
    float* __restrict__ out)
{
    const int t = threadIdx.x;
    float a = 0.f, b = 0.f;
    for (int i = t; i < B_; i += 256) { a += rowLoss[i]; b += rowCorr[i]; }
    __shared__ float sa[256], sb[256];
    sa[t] = a; sb[t] = b;
    __syncthreads();
    for (int s = 128; s; s >>= 1) {
        if (t < s) { sa[t] += sa[t + s]; sb[t] += sb[t + s]; }
        __syncthreads();
    }
    if (t == 0) {
        out[0] = sa[0] / ((float)B_ * (float)B_);
        out[1] = sb[0] / (float)B_;
    }
}

// ---------------------------------------------------------------------------
// Launch sequence
// ---------------------------------------------------------------------------
extern "C" void kernel_launch(void* const* d_in, const int* in_sizes, int n_in,
                              void* d_out, int out_size)
{
    (void)in_sizes; (void)n_in; (void)out_size;
    const float* target   = (const float*)d_in[0];
    const float* distr    = (const float*)d_in[1];
    const int*   start    = (const int*)  d_in[2];
    const float* emb_s    = (const float*)d_in[4];
    const float* Wih_s    = (const float*)d_in[5];
    const float* Whh_s    = (const float*)d_in[6];
    const float* bih_s    = (const float*)d_in[7];
    const float* bhh_s    = (const float*)d_in[8];
    const float* aff_s_W  = (const float*)d_in[9];
    const float* aff_s_b  = (const float*)d_in[10];
    const float* probs_W  = (const float*)d_in[11];
    const float* probs_b  = (const float*)d_in[12];
    const float* emb_r    = (const float*)d_in[13];
    const float* Wih_r    = (const float*)d_in[14];
    const float* Whh_r    = (const float*)d_in[15];
    const float* bih_r    = (const float*)d_in[16];
    const float* bhh_r    = (const float*)d_in[17];
    const float* aff_r_W  = (const float*)d_in[18];
    const float* aff_r_b  = (const float*)d_in[19];
    float* out = (float*)d_out;

    float *x, *h, *c, *gates, *logits, *lp, *r, *ts, *ds, *rowLoss, *rowCorr;
    int* msg;
    cudaGetSymbolAddress((void**)&x,       g_x);
    cudaGetSymbolAddress((void**)&h,       g_h);
    cudaGetSymbolAddress((void**)&c,       g_c);
    cudaGetSymbolAddress((void**)&gates,   g_gates);
    cudaGetSymbolAddress((void**)&logits,  g_logits);
    cudaGetSymbolAddress((void**)&msg,     g_msg);
    cudaGetSymbolAddress((void**)&lp,      g_lp);
    cudaGetSymbolAddress((void**)&r,       g_r);
    cudaGetSymbolAddress((void**)&ts,      g_ts);
    cudaGetSymbolAddress((void**)&ds,      g_ds);
    cudaGetSymbolAddress((void**)&rowLoss, g_rowLoss);
    cudaGetSymbolAddress((void**)&rowCorr, g_rowCorr);

    cudaFuncSetAttribute(gemm_mma, cudaFuncAttributeMaxDynamicSharedMemorySize, GEMM_SMEM);

    const float* NUL = (const float*)0;
    const dim3 gGate(FOURH / 128, B_ / 128);       // 32 x 8
    const dim3 gLogit((V_ + 127) / 128, B_ / 128); // 157 x 8

    // ---- Sender ----
    gemm_mma<<<dim3(H_ / 128, B_ / 128), 256, GEMM_SMEM>>>(
        target, aff_s_W, F_, NUL, NUL, 0, aff_s_b, NUL, h, B_, H_);
    cudaMemsetAsync(c, 0, sizeof(float) * B_ * H_);
    init_x0<<<(B_ * E_) / 256, 256>>>(emb_s, start, x);

    for (int t = 0; t < L_; t++) {
        gemm_mma<<<gGate, 256, GEMM_SMEM>>>(
            x, Wih_s, E_, h, Whh_s, H_, bih_s, bhh_s, gates, B_, FOURH);
        lstm_update<<<(B_ * H_) / 256, 256>>>(gates, h, c);
        gemm_mma<<<gLogit, 256, GEMM_SMEM>>>(
            h, probs_W, H_, NUL, NUL, 0, probs_b, NUL, logits, B_, V_);
        row_argmax_lse<<<B_, 256>>>(logits, msg + t * B_, lp);
        if (t + 1 < L_) gather_emb<<<(B_ * E_) / 256, 256>>>(emb_s, msg + t * B_, x);
    }

    // ---- Receiver ----
    cudaMemsetAsync(h, 0, sizeof(float) * B_ * H_);
    cudaMemsetAsync(c, 0, sizeof(float) * B_ * H_);
    for (int t = 0; t < L_; t++) {
        gather_emb<<<(B_ * E_) / 256, 256>>>(emb_r, msg + t * B_, x);
        gemm_mma<<<gGate, 256, GEMM_SMEM>>>(
            x, Wih_r, E_, h, Whh_r, H_, bih_r, bhh_r, gates, B_, FOURH);
        lstm_update<<<(B_ * H_) / 256, 256>>>(gates, h, c);
    }

    // ---- Scores + loss/accuracy ----
    gemm_mma<<<dim3(F_ / 128, B_ / 128), 256, GEMM_SMEM>>>(
        h, aff_r_W, H_, NUL, NUL, 0, aff_r_b, NUL, r, B_, F_);
    gemm_mma<<<dim3(B_ / 128, B_ / 128), 256, GEMM_SMEM>>>(
        target, r, F_, NUL, NUL, 0, NUL, NUL, ts, B_, B_);
    gemm_mma<<<dim3(B_ / 128, (D_ * B_) / 128), 256, GEMM_SMEM>>>(
        distr, r, F_, NUL, NUL, 0, NUL, NUL, ds, D_ * B_, B_);
    loss_acc_rows<<<B_, 256>>>(ts, ds, lp, rowLoss, rowCorr);
    finalize_k<<<1, 256>>>(rowLoss, rowCorr, out);
}